// round 14
// baseline (speedup 1.0000x reference)
#include <cuda_runtime.h>
#include <math.h>

// Problem constants (static per the reference module)
#define BB      4
#define NPER    2000
#define NPAD    2048          // padded table length: 8 tiles x 256; padding is
                              // zero-init and contributes exactly 0
#define NATOMS  (BB*NPER)
#define NN      11            // n = 0..10 per axis
#define NT      128           // threads per k_main block

#define KSQ_MAX_F   9.8696044010893586f   // fp32(pi^2), as JAX compares
#define TWOPI_F     6.2831854820251465f
#define INV_SELF    0.0634936359342410f   // 1/(sigma*(2*pi)^1.5)
#define NORM_F      90.0474f
#define EPS_F       1e-6f

typedef unsigned long long u64;

__device__ __forceinline__ u64 pk(float lo, float hi) {
    u64 r; asm("mov.b64 %0, {%1, %2};" : "=l"(r) : "f"(lo), "f"(hi)); return r;
}
__device__ __forceinline__ float2 upk(u64 v) {
    float lo, hi; asm("mov.b64 {%0, %1}, %2;" : "=f"(lo), "=f"(hi) : "l"(v));
    return make_float2(lo, hi);
}
__device__ __forceinline__ void fma2(u64& d, u64 a, u64 b) {
    asm("fma.rn.f32x2 %0, %1, %2, %0;" : "+l"(d) : "l"(a), "l"(b));
}
__device__ __forceinline__ u64 add2(u64 a, u64 b) {
    u64 d; asm("add.rn.f32x2 %0, %1, %2;" : "=l"(d) : "l"(a), "l"(b)); return d;
}

// fast sinpi/cospi on f in [-0.5, 0.5] (Taylor, max err ~3.6e-6 abs)
__device__ __forceinline__ void sincospi_fast(float f, float* s, float* c) {
    float t = f * f;
    float sp = fmaf(t, 0.0821458866f, -0.599264529f);
    sp = fmaf(t, sp, 2.55016404f);
    sp = fmaf(t, sp, -5.16771278f);
    sp = fmaf(t, sp, 3.14159265f);
    *s = f * sp;
    float cp = fmaf(t, -0.0258068917f, 0.235330631f);
    cp = fmaf(t, cp, -1.33526277f);
    cp = fmaf(t, cp, 4.05871213f);
    cp = fmaf(t, cp, -4.93480220f);
    *c = fmaf(t, cp, 1.0f);
}

// full-range: angle = 2*pi*f with f in [-0.5,0.5]
__device__ __forceinline__ void sc_2pi(float f, float* s, float* c) {
    float x = 2.0f * f;               // in [-1, 1]
    float xr = x - rintf(x);          // in [-0.5, 0.5]
    float par = x - xr;               // -1, 0, +1
    sincospi_fast(xr, s, c);
    if (par != 0.0f) { *s = -*s; *c = -*c; }
}

// ---------------- device scratch (zero-initialized; padding stays 0) ----------
__device__ float    g_cinv[BB][3][3];
__device__ float    g_vol[BB];
__device__ float    g_pot[BB];
__device__ unsigned g_cnt[BB];
__device__ __align__(16) float2 g_tabx[BB][NN][NPAD];   // q * e^{i 2pi n s0}
__device__ __align__(16) float2 g_taby[BB][NN][NPAD];   //     e^{i 2pi n s1}
__device__ __align__(16) float4 g_tabz[BB][NPAD];       // {Ez1, Ez3}

// ---------------- kernel 1: phase tables ----------------
// gy 0..2 : x-axis, n in {4g .. 4g+3} (g=2: 3 entries), seed sincos + recurrence
// gy 3..5 : y-axis likewise
// gy 6    : z seeds {Ez1, Ez3} + per-batch constants
__global__ void k_tab(const float* __restrict__ q, const float* __restrict__ r,
                      const float* __restrict__ cell) {
    int gy = blockIdx.y;
    int ga = blockIdx.x * blockDim.x + threadIdx.x;
    if (ga >= NATOMS) return;
    int b = ga / NPER;
    int a = ga - b * NPER;

    const float* m = cell + b * 9;
    float m00=m[0], m01=m[1], m02=m[2];
    float m10=m[3], m11=m[4], m12=m[5];
    float m20=m[6], m21=m[7], m22=m[8];
    float c00 = m11*m22 - m12*m21;
    float c01 = m12*m20 - m10*m22;
    float c02 = m10*m21 - m11*m20;
    float det = m00*c00 + m01*c01 + m02*c02;
    float inv = 1.0f / det;
    float i00 = c00 * inv;
    float i01 = (m02*m21 - m01*m22) * inv;
    float i02 = (m01*m12 - m02*m11) * inv;
    float i10 = c01 * inv;
    float i11 = (m00*m22 - m02*m20) * inv;
    float i12 = (m02*m10 - m00*m12) * inv;
    float i20 = c02 * inv;
    float i21 = (m01*m20 - m00*m21) * inv;
    float i22 = (m00*m11 - m01*m10) * inv;

    float r0 = r[3*ga+0], r1 = r[3*ga+1], r2 = r[3*ga+2];

    if (gy == 6) {
        if (a == 0) {
            g_cinv[b][0][0]=i00; g_cinv[b][0][1]=i01; g_cinv[b][0][2]=i02;
            g_cinv[b][1][0]=i10; g_cinv[b][1][1]=i11; g_cinv[b][1][2]=i12;
            g_cinv[b][2][0]=i20; g_cinv[b][2][1]=i21; g_cinv[b][2][2]=i22;
            g_vol[b] = det;
            g_pot[b] = 0.0f;
            g_cnt[b] = 0u;
        }
        float s2 = r0*i02 + r1*i12 + r2*i22;
        float f = s2 - rintf(s2);
        float si, co; sc_2pi(f, &si, &co);
        float e2r = co*co - si*si,   e2i = 2.0f*co*si;
        float e3r = e2r*co - e2i*si, e3i = e2r*si + e2i*co;
        g_tabz[b][a] = make_float4(co, si, e3r, e3i);
    } else {
        int axis = gy / 3;                 // 0: x, 1: y
        int g    = gy - axis * 3;          // group
        int n0   = 4 * g;                  // first n of group
        int cnt  = (g == 2) ? 3 : 4;

        float s = axis == 0 ? (r0*i00 + r1*i10 + r2*i20)
                            : (r0*i01 + r1*i11 + r2*i21);
        float f1 = s - rintf(s);
        float e1s, e1c; sc_2pi(f1, &e1s, &e1c);
        float Er, Ei;
        if (n0 == 0) { Er = 1.0f; Ei = 0.0f; }
        else {
            float u = (float)n0 * s;
            float f = u - rintf(u);
            sc_2pi(f, &Ei, &Er);
        }
        if (axis == 0) {                   // fold q into X
            float qv = q[ga];
            Er *= qv; Ei *= qv;
        }
        float2* __restrict__ dst = axis == 0 ? &g_tabx[b][0][0] : &g_taby[b][0][0];
        #pragma unroll
        for (int k = 0; k < 4; k++) {
            if (k < cnt) {
                dst[(n0 + k) * NPAD + a] = make_float2(Er, Ei);
                float t = Er*e1c - Ei*e1s; Ei = Er*e1s + Ei*e1c; Er = t;
            }
        }
    }
}

// ---------------- smem tile (256 atoms) ----------------
struct Tile {
    float2 x[256];
    float2 y[256];
    float4 z[256];
};

__device__ __forceinline__ void stage_tile(const float2* __restrict__ tx,
        const float2* __restrict__ ty, const float4* __restrict__ tz,
        Tile& t, int tile, int tid) {
    const float4* xs = reinterpret_cast<const float4*>(tx) + tile * 128;
    const float4* ys = reinterpret_cast<const float4*>(ty) + tile * 128;
    const float4* zs = tz + tile * 256;
    float4 xv  = xs[tid];
    float4 yv  = ys[tid];
    float4 zv0 = zs[tid];
    float4 zv1 = zs[tid + 128];
    reinterpret_cast<float4*>(t.x)[tid] = xv;
    reinterpret_cast<float4*>(t.y)[tid] = yv;
    t.z[tid]       = zv0;
    t.z[tid + 128] = zv1;
}

// ---------------- per-atom update ----------------
template<int S, int MC>
__device__ __forceinline__ void process_atom(float2 X, float2 Y, float4 Z,
        u64& C0, u64& C1, u64* U0, u64* V0, u64* U1, u64* V1) {
    float p  = X.x*Y.x, qq = X.y*Y.y, rr = X.x*Y.y, ss = X.y*Y.x;
    float ar0 = p - qq, ar1 = p + qq;   // n2 = +m2 / -m2
    float ai0 = rr + ss, ai1 = ss - rr;
    u64 a0 = pk(ar0, ai0), a1 = pk(ar1, ai1);
    if (!S) { C0 = add2(C0, a0); C1 = add2(C1, a1); }

    if (MC > 0) {
        float z1r = Z.x, z1i = Z.y, z3r = Z.z, z3i = Z.w;
        float zr[5], zi[5];
        float z2r = 0.f, z2i = 0.f, z4r = 0.f, z4i = 0.f;
        if ((!S && MC >= 2) || (S && MC >= 3)) {
            z2r = fmaf(z1r, z1r, -z1i*z1i);
            z2i = 2.0f * z1r * z1i;
        }
        if ((!S && MC >= 4) || (S && MC >= 5)) {
            z4r = fmaf(z3r, z1r, -z3i*z1i);
            z4i = fmaf(z3r, z1i, z3i*z1r);
        }
        if (!S) {
            zr[0] = z1r; zi[0] = z1i;
            if (MC >= 2) { zr[1] = z2r; zi[1] = z2i; }
            if (MC >= 3) { zr[2] = z3r; zi[2] = z3i; }
            if (MC >= 4) { zr[3] = z4r; zi[3] = z4i; }
            if (MC >= 5) { zr[4] = fmaf(z3r, z2r, -z3i*z2i);
                           zi[4] = fmaf(z3r, z2i, z3i*z2r); }
        } else {
            float z6r = fmaf(z3r, z3r, -z3i*z3i), z6i = 2.0f*z3r*z3i;
            zr[0] = z6r; zi[0] = z6i;
            if (MC >= 2) { zr[1] = fmaf(z6r, z1r, -z6i*z1i);
                           zi[1] = fmaf(z6r, z1i, z6i*z1r); }
            if (MC >= 3) { zr[2] = fmaf(z6r, z2r, -z6i*z2i);
                           zi[2] = fmaf(z6r, z2i, z6i*z2r); }
            if (MC >= 4) { zr[3] = fmaf(z6r, z3r, -z6i*z3i);
                           zi[3] = fmaf(z6r, z3i, z6i*z3r); }
            if (MC >= 5) { zr[4] = fmaf(z6r, z4r, -z6i*z4i);
                           zi[4] = fmaf(z6r, z4i, z6i*z4r); }
        }
        #pragma unroll
        for (int mi = 0; mi < MC; mi++) {
            u64 ZR = pk(zr[mi], zr[mi]), ZI = pk(zi[mi], zi[mi]);
            fma2(U0[mi], ZR, a0); fma2(V0[mi], ZI, a0);
            fma2(U1[mi], ZR, a1); fma2(V1[mi], ZI, a1);
        }
    }
}

// ---------------- atom loop: 8 double-buffered smem tiles, guard-free --------
template<int S, int MC>
__device__ __forceinline__ void atom_loop(int tid,
        const float2* __restrict__ tx, const float2* __restrict__ ty,
        const float4* __restrict__ tz, Tile* tiles,
        u64& C0, u64& C1, u64* U0, u64* V0, u64* U1, u64* V1) {
    stage_tile(tx, ty, tz, tiles[0], 0, tid);
    __syncthreads();
    #pragma unroll 2
    for (int tl = 0; tl < 8; tl++) {
        if (tl < 7) stage_tile(tx, ty, tz, tiles[(tl + 1) & 1], tl + 1, tid);
        Tile& cur = tiles[tl & 1];
        process_atom<S, MC>(cur.x[tid], cur.y[tid], cur.z[tid],
                            C0, C1, U0, V0, U1, V1);
        process_atom<S, MC>(cur.x[tid + 128], cur.y[tid + 128], cur.z[tid + 128],
                            C0, C1, U0, V0, U1, V1);
        __syncthreads();
    }
}

// ---------------- kernel 2 body ----------------
template<int S>
__device__ __forceinline__ void k_main_body(const float* __restrict__ q,
                                            float* __restrict__ out,
                                            float (*red)[44], float* cont,
                                            Tile* tiles) {
    int blk = blockIdx.x;
    int b   = blk / 121;
    int rem = blk - b * 121;
    int n1  = rem / 11;
    int m2  = rem - n1 * 11;
    int tid = threadIdx.x;

    constexpr int MLO = S ? 6 : 1;
    constexpr int ENT = S ? 10 : 11;    // weighted k-entries per n2-sign
    constexpr int NENT = S ? 20 : 22;   // packed complex entries
    constexpr int PB  = S ? 0 : 2;      // U/V bank base

    float g00 = TWOPI_F*g_cinv[b][0][0], g01 = TWOPI_F*g_cinv[b][1][0], g02 = TWOPI_F*g_cinv[b][2][0];
    float g10 = TWOPI_F*g_cinv[b][0][1], g11 = TWOPI_F*g_cinv[b][1][1], g12 = TWOPI_F*g_cinv[b][2][1];
    float g20 = TWOPI_F*g_cinv[b][0][2], g21 = TWOPI_F*g_cinv[b][1][2], g22 = TWOPI_F*g_cinv[b][2][2];

    // parallel selection: mmax = max in-cutoff |n3| (with slack), -1 if none
    __shared__ int s_sel;
    if (tid == 0) s_sel = -1;
    __syncthreads();
    if (tid < 42) {
        int sg = tid / 21, j = tid - sg * 21;
        int n3i = j - 10;
        float fn2 = sg ? -(float)m2 : (float)m2;
        float n3 = (float)n3i;
        float kv0 = n1*g00 + fn2*g01 + n3*g02;
        float kv1 = n1*g10 + fn2*g11 + n3*g12;
        float kv2 = n1*g20 + fn2*g21 + n3*g22;
        float ksq = kv0*kv0 + kv1*kv1 + kv2*kv2;
        if (ksq > 0.0f && ksq <= KSQ_MAX_F * 1.001f)
            atomicMax(&s_sel, n3i < 0 ? -n3i : n3i);
    }
    __syncthreads();
    int  mmax   = s_sel;
    bool active = S ? (mmax >= 6) : (mmax >= 0);

    if (active) {
        const float2* __restrict__ tx = &g_tabx[b][n1][0];
        const float2* __restrict__ ty = &g_taby[b][m2][0];
        const float4* __restrict__ tz = &g_tabz[b][0];

        u64 C0 = 0, C1 = 0;
        u64 U0[5], V0[5], U1[5], V1[5];
        #pragma unroll
        for (int m = 0; m < 5; m++) { U0[m]=0; V0[m]=0; U1[m]=0; V1[m]=0; }

        int mcnt = S ? (mmax - 5) : (mmax < 5 ? mmax : 5);   // #m's this block
        switch (mcnt) {
            case 0: if (!S) atom_loop<S,0>(tid, tx, ty, tz, tiles, C0, C1, U0, V0, U1, V1); break;
            case 1: atom_loop<S,1>(tid, tx, ty, tz, tiles, C0, C1, U0, V0, U1, V1); break;
            case 2: atom_loop<S,2>(tid, tx, ty, tz, tiles, C0, C1, U0, V0, U1, V1); break;
            case 3: atom_loop<S,3>(tid, tx, ty, tz, tiles, C0, C1, U0, V0, U1, V1); break;
            case 4: atom_loop<S,4>(tid, tx, ty, tz, tiles, C0, C1, U0, V0, U1, V1); break;
            default: atom_loop<S,5>(tid, tx, ty, tz, tiles, C0, C1, U0, V0, U1, V1); break;
        }

        // ---- pack entries, 3-level warp reduce -> 16 partials in smem ----
        u64 packed[NENT];
        if (!S) { packed[0] = C0; packed[1] = C1; }
        #pragma unroll
        for (int m = 0; m < 5; m++) {
            packed[PB + 2*m]          = U0[m];
            packed[PB + 2*m + 1]      = V0[m];
            packed[PB + 10 + 2*m]     = U1[m];
            packed[PB + 10 + 2*m + 1] = V1[m];
        }
        int w = tid >> 5, lane = tid & 31;
        #pragma unroll
        for (int j = 0; j < NENT; j++) {
            u64 v = packed[j];
            v = add2(v, __shfl_xor_sync(0xffffffffu, v, 16));
            v = add2(v, __shfl_xor_sync(0xffffffffu, v, 8));
            v = add2(v, __shfl_xor_sync(0xffffffffu, v, 4));
            if (lane < 4) {
                float2 f2 = upk(v);
                red[w*4 + lane][2*j]   = f2.x;
                red[w*4 + lane][2*j+1] = f2.y;
            }
        }
        __syncthreads();

        // ---- per-kpoint weighting (verbatim mask math), all in warp 0 ----
        if (tid < 32) {
            float c = 0.0f;
            if (tid < 2 * ENT) {
                int sgn = tid / ENT, j = tid - sgn * ENT;
                if (!(m2 == 0 && sgn == 1)) {         // n2 = -0 duplicates +0
                    int n3i;
                    float Sr, Si;
                    if (!S && j == 0) {
                        n3i = 0;
                        int o = sgn;
                        float cr = 0.0f, ci = 0.0f;
                        #pragma unroll
                        for (int pI = 0; pI < 16; pI++) {
                            cr += red[pI][2*o];
                            ci += red[pI][2*o+1];
                        }
                        Sr = cr; Si = ci;
                    } else {
                        int jj = S ? j : (j - 1);      // 0..9
                        bool isP = (jj < 5);
                        int  mi  = isP ? jj : (jj - 5);
                        n3i = isP ? (MLO + mi) : -(MLO + mi);
                        int ob = PB + sgn*10 + 2*mi;   // U entry index
                        float Ur = 0.0f, Ui = 0.0f, Vr = 0.0f, Vi = 0.0f;
                        #pragma unroll
                        for (int pI = 0; pI < 16; pI++) {
                            Ur += red[pI][2*ob];
                            Ui += red[pI][2*ob+1];
                            Vr += red[pI][2*ob+2];
                            Vi += red[pI][2*ob+3];
                        }
                        if (isP) { Sr = Ur - Vi; Si = Ui + Vr; }   // S(+m) = U + iV
                        else     { Sr = Ur + Vi; Si = Ui - Vr; }   // S(-m) = U - iV
                    }
                    float fn2 = sgn ? -(float)m2 : (float)m2;
                    float n3  = (float)n3i;
                    float kv0 = n1*g00 + fn2*g01 + n3*g02;
                    float kv1 = n1*g10 + fn2*g11 + n3*g12;
                    float kv2 = n1*g20 + fn2*g21 + n3*g22;
                    float ksq = kv0*kv0 + kv1*kv1 + kv2*kv2;
                    if (ksq > 0.0f && ksq <= KSQ_MAX_F) {
                        float wgt  = (n1 > 0) ? 2.0f : 1.0f;
                        float kfac = expf(-0.5f * ksq) / (ksq + EPS_F);
                        c = wgt * kfac * (Sr*Sr + Si*Si);
                    }
                }
            }
            c += __shfl_xor_sync(0xffffffffu, c, 16);
            c += __shfl_xor_sync(0xffffffffu, c, 8);
            c += __shfl_xor_sync(0xffffffffu, c, 4);
            c += __shfl_xor_sync(0xffffffffu, c, 2);
            c += __shfl_xor_sync(0xffffffffu, c, 1);
            if (tid == 0) atomicAdd(&g_pot[b], c);
        }
    }

    // ---- fused finalization: last of 242 blocks for this batch writes out[b] ----
    __shared__ bool s_last;
    if (tid == 0) {
        __threadfence();
        unsigned old = atomicAdd(&g_cnt[b], 1u);
        s_last = (old == 241u);
    }
    __syncthreads();
    if (s_last) {
        float s = 0.0f;
        for (int a2 = tid; a2 < NPER; a2 += NT) {
            float qv = q[b * NPER + a2];
            s += qv * qv;
        }
        cont[tid] = s;
        __syncthreads();
        #pragma unroll
        for (int t2 = NT/2; t2 > 0; t2 >>= 1) {
            if (tid < t2) cont[tid] += cont[tid + t2];
            __syncthreads();
        }
        if (tid == 0) {
            float potv = atomicAdd(&g_pot[b], 0.0f);   // coherent read
            float pot = potv / g_vol[b] - cont[0] * INV_SELF;
            out[b] = pot * NORM_F;
        }
    }
}

__global__ void __launch_bounds__(NT) k_main(const float* __restrict__ q,
                                             float* __restrict__ out) {
    __shared__ float red[16][44];
    __shared__ float cont[NT];
    __shared__ Tile tiles[2];
    if (blockIdx.y == 0) k_main_body<0>(q, out, red, cont, tiles);
    else                 k_main_body<1>(q, out, red, cont, tiles);
}

// ---------------- launch ----------------
extern "C" void kernel_launch(void* const* d_in, const int* in_sizes, int n_in,
                              void* d_out, int out_size) {
    const float* q    = (const float*)d_in[0];
    const float* r    = (const float*)d_in[1];
    const float* cell = (const float*)d_in[2];
    float* out = (float*)d_out;

    dim3 tgrid((NATOMS + 255) / 256, 7);
    k_tab<<<tgrid, 256>>>(q, r, cell);
    k_main<<<dim3(BB * 121, 2), NT>>>(q, out);
}

// round 15
// speedup vs baseline: 1.0250x; 1.0250x over previous
#include <cuda_runtime.h>
#include <math.h>

// Problem constants (static per the reference module)
#define BB      4
#define NPER    2000
#define NPAD    2048          // padded table length: 8 tiles x 256; padding is
                              // zero-init and contributes exactly 0
#define NATOMS  (BB*NPER)
#define NN      11            // n = 0..10 per axis
#define NT      128           // threads per k_main block

#define KSQ_MAX_F   9.8696044010893586f   // fp32(pi^2), as JAX compares
#define TWOPI_F     6.2831854820251465f
#define INV_SELF    0.0634936359342410f   // 1/(sigma*(2*pi)^1.5)
#define NORM_F      90.0474f
#define EPS_F       1e-6f

typedef unsigned long long u64;

__device__ __forceinline__ u64 pk(float lo, float hi) {
    u64 r; asm("mov.b64 %0, {%1, %2};" : "=l"(r) : "f"(lo), "f"(hi)); return r;
}
__device__ __forceinline__ float2 upk(u64 v) {
    float lo, hi; asm("mov.b64 {%0, %1}, %2;" : "=f"(lo), "=f"(hi) : "l"(v));
    return make_float2(lo, hi);
}
__device__ __forceinline__ void fma2(u64& d, u64 a, u64 b) {
    asm("fma.rn.f32x2 %0, %1, %2, %0;" : "+l"(d) : "l"(a), "l"(b));
}
__device__ __forceinline__ u64 add2(u64 a, u64 b) {
    u64 d; asm("add.rn.f32x2 %0, %1, %2;" : "=l"(d) : "l"(a), "l"(b)); return d;
}

// async global->shared 16B copy
__device__ __forceinline__ void cp16(unsigned dst, const void* src) {
    asm volatile("cp.async.cg.shared.global [%0], [%1], 16;"
                 :: "r"(dst), "l"(src) : "memory");
}
#define CP_COMMIT() asm volatile("cp.async.commit_group;" ::: "memory")
#define CP_WAIT1()  asm volatile("cp.async.wait_group 1;" ::: "memory")
#define CP_WAIT0()  asm volatile("cp.async.wait_group 0;" ::: "memory")

// fast sinpi/cospi on f in [-0.5, 0.5] (Taylor, max err ~3.6e-6 abs)
__device__ __forceinline__ void sincospi_fast(float f, float* s, float* c) {
    float t = f * f;
    float sp = fmaf(t, 0.0821458866f, -0.599264529f);
    sp = fmaf(t, sp, 2.55016404f);
    sp = fmaf(t, sp, -5.16771278f);
    sp = fmaf(t, sp, 3.14159265f);
    *s = f * sp;
    float cp = fmaf(t, -0.0258068917f, 0.235330631f);
    cp = fmaf(t, cp, -1.33526277f);
    cp = fmaf(t, cp, 4.05871213f);
    cp = fmaf(t, cp, -4.93480220f);
    *c = fmaf(t, cp, 1.0f);
}

// full-range: angle = 2*pi*f with f in [-0.5,0.5]
__device__ __forceinline__ void sc_2pi(float f, float* s, float* c) {
    float x = 2.0f * f;               // in [-1, 1]
    float xr = x - rintf(x);          // in [-0.5, 0.5]
    float par = x - xr;               // -1, 0, +1
    sincospi_fast(xr, s, c);
    if (par != 0.0f) { *s = -*s; *c = -*c; }
}

// ---------------- device scratch (zero-initialized; padding stays 0) ----------
__device__ float    g_cinv[BB][3][3];
__device__ float    g_vol[BB];
__device__ float    g_pot[BB];
__device__ unsigned g_cnt[BB];
__device__ __align__(16) float2 g_tabx[BB][NN][NPAD];   // q * e^{i 2pi n s0}
__device__ __align__(16) float2 g_taby[BB][NN][NPAD];   //     e^{i 2pi n s1}
__device__ __align__(16) float4 g_tabz[BB][NPAD];       // {Ez1, Ez3}

// ---------------- kernel 1: phase tables ----------------
// gy 0..2 : x-axis, n in {4g .. 4g+3} (g=2: 3 entries), seed sincos + recurrence
// gy 3..5 : y-axis likewise
// gy 6    : z seeds {Ez1, Ez3} + per-batch constants
__global__ void k_tab(const float* __restrict__ q, const float* __restrict__ r,
                      const float* __restrict__ cell) {
    int gy = blockIdx.y;
    int ga = blockIdx.x * blockDim.x + threadIdx.x;
    if (ga >= NATOMS) return;
    int b = ga / NPER;
    int a = ga - b * NPER;

    const float* m = cell + b * 9;
    float m00=m[0], m01=m[1], m02=m[2];
    float m10=m[3], m11=m[4], m12=m[5];
    float m20=m[6], m21=m[7], m22=m[8];
    float c00 = m11*m22 - m12*m21;
    float c01 = m12*m20 - m10*m22;
    float c02 = m10*m21 - m11*m20;
    float det = m00*c00 + m01*c01 + m02*c02;
    float inv = 1.0f / det;
    float i00 = c00 * inv;
    float i01 = (m02*m21 - m01*m22) * inv;
    float i02 = (m01*m12 - m02*m11) * inv;
    float i10 = c01 * inv;
    float i11 = (m00*m22 - m02*m20) * inv;
    float i12 = (m02*m10 - m00*m12) * inv;
    float i20 = c02 * inv;
    float i21 = (m01*m20 - m00*m21) * inv;
    float i22 = (m00*m11 - m01*m10) * inv;

    float r0 = r[3*ga+0], r1 = r[3*ga+1], r2 = r[3*ga+2];

    if (gy == 6) {
        if (a == 0) {
            g_cinv[b][0][0]=i00; g_cinv[b][0][1]=i01; g_cinv[b][0][2]=i02;
            g_cinv[b][1][0]=i10; g_cinv[b][1][1]=i11; g_cinv[b][1][2]=i12;
            g_cinv[b][2][0]=i20; g_cinv[b][2][1]=i21; g_cinv[b][2][2]=i22;
            g_vol[b] = det;
            g_pot[b] = 0.0f;
            g_cnt[b] = 0u;
        }
        float s2 = r0*i02 + r1*i12 + r2*i22;
        float f = s2 - rintf(s2);
        float si, co; sc_2pi(f, &si, &co);
        float e2r = co*co - si*si,   e2i = 2.0f*co*si;
        float e3r = e2r*co - e2i*si, e3i = e2r*si + e2i*co;
        g_tabz[b][a] = make_float4(co, si, e3r, e3i);
    } else {
        int axis = gy / 3;                 // 0: x, 1: y
        int g    = gy - axis * 3;          // group
        int n0   = 4 * g;                  // first n of group
        int cnt  = (g == 2) ? 3 : 4;

        float s = axis == 0 ? (r0*i00 + r1*i10 + r2*i20)
                            : (r0*i01 + r1*i11 + r2*i21);
        float f1 = s - rintf(s);
        float e1s, e1c; sc_2pi(f1, &e1s, &e1c);
        float Er, Ei;
        if (n0 == 0) { Er = 1.0f; Ei = 0.0f; }
        else {
            float u = (float)n0 * s;
            float f = u - rintf(u);
            sc_2pi(f, &Ei, &Er);
        }
        if (axis == 0) {                   // fold q into X
            float qv = q[ga];
            Er *= qv; Ei *= qv;
        }
        float2* __restrict__ dst = axis == 0 ? &g_tabx[b][0][0] : &g_taby[b][0][0];
        #pragma unroll
        for (int k = 0; k < 4; k++) {
            if (k < cnt) {
                dst[(n0 + k) * NPAD + a] = make_float2(Er, Ei);
                float t = Er*e1c - Ei*e1s; Ei = Er*e1s + Ei*e1c; Er = t;
            }
        }
    }
}

// ---------------- smem tile (256 atoms) ----------------
struct Tile {
    float2 x[256];   // 2048 B
    float2 y[256];   // 2048 B
    float4 z[256];   // 4096 B
};

// async staging: 4 x cp.async 16B per thread, no register wait
__device__ __forceinline__ void stage_tile_async(const float2* __restrict__ tx,
        const float2* __restrict__ ty, const float4* __restrict__ tz,
        Tile& t, int tile, int tid) {
    unsigned tb = (unsigned)__cvta_generic_to_shared(&t);
    const float4* xs = reinterpret_cast<const float4*>(tx) + tile * 128;
    const float4* ys = reinterpret_cast<const float4*>(ty) + tile * 128;
    const float4* zs = tz + tile * 256;
    cp16(tb + tid * 16,               xs + tid);
    cp16(tb + 2048 + tid * 16,        ys + tid);
    cp16(tb + 4096 + tid * 16,        zs + tid);
    cp16(tb + 4096 + 2048 + tid * 16, zs + tid + 128);
}

// ---------------- per-atom update ----------------
template<int S, int MC>
__device__ __forceinline__ void process_atom(float2 X, float2 Y, float4 Z,
        u64& C0, u64& C1, u64* U0, u64* V0, u64* U1, u64* V1) {
    float p  = X.x*Y.x, qq = X.y*Y.y, rr = X.x*Y.y, ss = X.y*Y.x;
    float ar0 = p - qq, ar1 = p + qq;   // n2 = +m2 / -m2
    float ai0 = rr + ss, ai1 = ss - rr;
    u64 a0 = pk(ar0, ai0), a1 = pk(ar1, ai1);
    if (!S) { C0 = add2(C0, a0); C1 = add2(C1, a1); }

    if (MC > 0) {
        float z1r = Z.x, z1i = Z.y, z3r = Z.z, z3i = Z.w;
        float zr[5], zi[5];
        float z2r = 0.f, z2i = 0.f, z4r = 0.f, z4i = 0.f;
        if ((!S && MC >= 2) || (S && MC >= 3)) {
            z2r = fmaf(z1r, z1r, -z1i*z1i);
            z2i = 2.0f * z1r * z1i;
        }
        if ((!S && MC >= 4) || (S && MC >= 5)) {
            z4r = fmaf(z3r, z1r, -z3i*z1i);
            z4i = fmaf(z3r, z1i, z3i*z1r);
        }
        if (!S) {
            zr[0] = z1r; zi[0] = z1i;
            if (MC >= 2) { zr[1] = z2r; zi[1] = z2i; }
            if (MC >= 3) { zr[2] = z3r; zi[2] = z3i; }
            if (MC >= 4) { zr[3] = z4r; zi[3] = z4i; }
            if (MC >= 5) { zr[4] = fmaf(z3r, z2r, -z3i*z2i);
                           zi[4] = fmaf(z3r, z2i, z3i*z2r); }
        } else {
            float z6r = fmaf(z3r, z3r, -z3i*z3i), z6i = 2.0f*z3r*z3i;
            zr[0] = z6r; zi[0] = z6i;
            if (MC >= 2) { zr[1] = fmaf(z6r, z1r, -z6i*z1i);
                           zi[1] = fmaf(z6r, z1i, z6i*z1r); }
            if (MC >= 3) { zr[2] = fmaf(z6r, z2r, -z6i*z2i);
                           zi[2] = fmaf(z6r, z2i, z6i*z2r); }
            if (MC >= 4) { zr[3] = fmaf(z6r, z3r, -z6i*z3i);
                           zi[3] = fmaf(z6r, z3i, z6i*z3r); }
            if (MC >= 5) { zr[4] = fmaf(z6r, z4r, -z6i*z4i);
                           zi[4] = fmaf(z6r, z4i, z6i*z4r); }
        }
        #pragma unroll
        for (int mi = 0; mi < MC; mi++) {
            u64 ZR = pk(zr[mi], zr[mi]), ZI = pk(zi[mi], zi[mi]);
            fma2(U0[mi], ZR, a0); fma2(V0[mi], ZI, a0);
            fma2(U1[mi], ZR, a1); fma2(V1[mi], ZI, a1);
        }
    }
}

// ---------------- atom loop: 8 cp.async double-buffered tiles, guard-free ------
template<int S, int MC>
__device__ __forceinline__ void atom_loop(int tid,
        const float2* __restrict__ tx, const float2* __restrict__ ty,
        const float4* __restrict__ tz, Tile* tiles,
        u64& C0, u64& C1, u64* U0, u64* V0, u64* U1, u64* V1) {
    stage_tile_async(tx, ty, tz, tiles[0], 0, tid); CP_COMMIT();
    stage_tile_async(tx, ty, tz, tiles[1], 1, tid); CP_COMMIT();
    #pragma unroll
    for (int tl = 0; tl < 8; tl++) {
        if (tl < 7) { CP_WAIT1(); } else { CP_WAIT0(); }
        __syncthreads();                       // tile tl visible block-wide
        Tile& cur = tiles[tl & 1];
        process_atom<S, MC>(cur.x[tid], cur.y[tid], cur.z[tid],
                            C0, C1, U0, V0, U1, V1);
        process_atom<S, MC>(cur.x[tid + 128], cur.y[tid + 128], cur.z[tid + 128],
                            C0, C1, U0, V0, U1, V1);
        __syncthreads();                       // all done reading this buffer
        if (tl < 6) {
            stage_tile_async(tx, ty, tz, tiles[tl & 1], tl + 2, tid);
            CP_COMMIT();
        }
    }
}

// ---------------- kernel 2 body ----------------
template<int S>
__device__ __forceinline__ void k_main_body(const float* __restrict__ q,
                                            float* __restrict__ out,
                                            float (*red)[44], float* cont,
                                            Tile* tiles) {
    int blk = blockIdx.x;
    int b   = blk / 121;
    int rem = blk - b * 121;
    int n1  = rem / 11;
    int m2  = rem - n1 * 11;
    int tid = threadIdx.x;

    constexpr int MLO = S ? 6 : 1;
    constexpr int ENT = S ? 10 : 11;    // weighted k-entries per n2-sign
    constexpr int NENT = S ? 20 : 22;   // packed complex entries
    constexpr int PB  = S ? 0 : 2;      // U/V bank base

    float g00 = TWOPI_F*g_cinv[b][0][0], g01 = TWOPI_F*g_cinv[b][1][0], g02 = TWOPI_F*g_cinv[b][2][0];
    float g10 = TWOPI_F*g_cinv[b][0][1], g11 = TWOPI_F*g_cinv[b][1][1], g12 = TWOPI_F*g_cinv[b][2][1];
    float g20 = TWOPI_F*g_cinv[b][0][2], g21 = TWOPI_F*g_cinv[b][1][2], g22 = TWOPI_F*g_cinv[b][2][2];

    // parallel selection: mmax = max in-cutoff |n3| (with slack), -1 if none
    __shared__ int s_sel;
    if (tid == 0) s_sel = -1;
    __syncthreads();
    if (tid < 42) {
        int sg = tid / 21, j = tid - sg * 21;
        int n3i = j - 10;
        float fn2 = sg ? -(float)m2 : (float)m2;
        float n3 = (float)n3i;
        float kv0 = n1*g00 + fn2*g01 + n3*g02;
        float kv1 = n1*g10 + fn2*g11 + n3*g12;
        float kv2 = n1*g20 + fn2*g21 + n3*g22;
        float ksq = kv0*kv0 + kv1*kv1 + kv2*kv2;
        if (ksq > 0.0f && ksq <= KSQ_MAX_F * 1.001f)
            atomicMax(&s_sel, n3i < 0 ? -n3i : n3i);
    }
    __syncthreads();
    int  mmax   = s_sel;
    bool active = S ? (mmax >= 6) : (mmax >= 0);

    if (active) {
        const float2* __restrict__ tx = &g_tabx[b][n1][0];
        const float2* __restrict__ ty = &g_taby[b][m2][0];
        const float4* __restrict__ tz = &g_tabz[b][0];

        u64 C0 = 0, C1 = 0;
        u64 U0[5], V0[5], U1[5], V1[5];
        #pragma unroll
        for (int m = 0; m < 5; m++) { U0[m]=0; V0[m]=0; U1[m]=0; V1[m]=0; }

        int mcnt = S ? (mmax - 5) : (mmax < 5 ? mmax : 5);   // #m's this block
        switch (mcnt) {
            case 0: if (!S) atom_loop<S,0>(tid, tx, ty, tz, tiles, C0, C1, U0, V0, U1, V1); break;
            case 1: atom_loop<S,1>(tid, tx, ty, tz, tiles, C0, C1, U0, V0, U1, V1); break;
            case 2: atom_loop<S,2>(tid, tx, ty, tz, tiles, C0, C1, U0, V0, U1, V1); break;
            case 3: atom_loop<S,3>(tid, tx, ty, tz, tiles, C0, C1, U0, V0, U1, V1); break;
            case 4: atom_loop<S,4>(tid, tx, ty, tz, tiles, C0, C1, U0, V0, U1, V1); break;
            default: atom_loop<S,5>(tid, tx, ty, tz, tiles, C0, C1, U0, V0, U1, V1); break;
        }

        // ---- pack entries, 3-level warp reduce -> 16 partials in smem ----
        u64 packed[NENT];
        if (!S) { packed[0] = C0; packed[1] = C1; }
        #pragma unroll
        for (int m = 0; m < 5; m++) {
            packed[PB + 2*m]          = U0[m];
            packed[PB + 2*m + 1]      = V0[m];
            packed[PB + 10 + 2*m]     = U1[m];
            packed[PB + 10 + 2*m + 1] = V1[m];
        }
        int w = tid >> 5, lane = tid & 31;
        #pragma unroll
        for (int j = 0; j < NENT; j++) {
            u64 v = packed[j];
            v = add2(v, __shfl_xor_sync(0xffffffffu, v, 16));
            v = add2(v, __shfl_xor_sync(0xffffffffu, v, 8));
            v = add2(v, __shfl_xor_sync(0xffffffffu, v, 4));
            if (lane < 4) {
                float2 f2 = upk(v);
                red[w*4 + lane][2*j]   = f2.x;
                red[w*4 + lane][2*j+1] = f2.y;
            }
        }
        __syncthreads();

        // ---- per-kpoint weighting (verbatim mask math), all in warp 0 ----
        if (tid < 32) {
            float c = 0.0f;
            if (tid < 2 * ENT) {
                int sgn = tid / ENT, j = tid - sgn * ENT;
                if (!(m2 == 0 && sgn == 1)) {         // n2 = -0 duplicates +0
                    int n3i;
                    float Sr, Si;
                    if (!S && j == 0) {
                        n3i = 0;
                        int o = sgn;
                        float cr = 0.0f, ci = 0.0f;
                        #pragma unroll
                        for (int pI = 0; pI < 16; pI++) {
                            cr += red[pI][2*o];
                            ci += red[pI][2*o+1];
                        }
                        Sr = cr; Si = ci;
                    } else {
                        int jj = S ? j : (j - 1);      // 0..9
                        bool isP = (jj < 5);
                        int  mi  = isP ? jj : (jj - 5);
                        n3i = isP ? (MLO + mi) : -(MLO + mi);
                        int ob = PB + sgn*10 + 2*mi;   // U entry index
                        float Ur = 0.0f, Ui = 0.0f, Vr = 0.0f, Vi = 0.0f;
                        #pragma unroll
                        for (int pI = 0; pI < 16; pI++) {
                            Ur += red[pI][2*ob];
                            Ui += red[pI][2*ob+1];
                            Vr += red[pI][2*ob+2];
                            Vi += red[pI][2*ob+3];
                        }
                        if (isP) { Sr = Ur - Vi; Si = Ui + Vr; }   // S(+m) = U + iV
                        else     { Sr = Ur + Vi; Si = Ui - Vr; }   // S(-m) = U - iV
                    }
                    float fn2 = sgn ? -(float)m2 : (float)m2;
                    float n3  = (float)n3i;
                    float kv0 = n1*g00 + fn2*g01 + n3*g02;
                    float kv1 = n1*g10 + fn2*g11 + n3*g12;
                    float kv2 = n1*g20 + fn2*g21 + n3*g22;
                    float ksq = kv0*kv0 + kv1*kv1 + kv2*kv2;
                    if (ksq > 0.0f && ksq <= KSQ_MAX_F) {
                        float wgt  = (n1 > 0) ? 2.0f : 1.0f;
                        float kfac = expf(-0.5f * ksq) / (ksq + EPS_F);
                        c = wgt * kfac * (Sr*Sr + Si*Si);
                    }
                }
            }
            c += __shfl_xor_sync(0xffffffffu, c, 16);
            c += __shfl_xor_sync(0xffffffffu, c, 8);
            c += __shfl_xor_sync(0xffffffffu, c, 4);
            c += __shfl_xor_sync(0xffffffffu, c, 2);
            c += __shfl_xor_sync(0xffffffffu, c, 1);
            if (tid == 0) atomicAdd(&g_pot[b], c);
        }
    }

    // ---- fused finalization: last of 242 blocks for this batch writes out[b] ----
    __shared__ bool s_last;
    if (tid == 0) {
        __threadfence();
        unsigned old = atomicAdd(&g_cnt[b], 1u);
        s_last = (old == 241u);
    }
    __syncthreads();
    if (s_last) {
        float s = 0.0f;
        for (int a2 = tid; a2 < NPER; a2 += NT) {
            float qv = q[b * NPER + a2];
            s += qv * qv;
        }
        cont[tid] = s;
        __syncthreads();
        #pragma unroll
        for (int t2 = NT/2; t2 > 0; t2 >>= 1) {
            if (tid < t2) cont[tid] += cont[tid + t2];
            __syncthreads();
        }
        if (tid == 0) {
            float potv = atomicAdd(&g_pot[b], 0.0f);   // coherent read
            float pot = potv / g_vol[b] - cont[0] * INV_SELF;
            out[b] = pot * NORM_F;
        }
    }
}

__global__ void __launch_bounds__(NT) k_main(const float* __restrict__ q,
                                             float* __restrict__ out) {
    __shared__ float red[16][44];
    __shared__ float cont[NT];
    __shared__ Tile tiles[2];
    if (blockIdx.y == 0) k_main_body<0>(q, out, red, cont, tiles);
    else                 k_main_body<1>(q, out, red, cont, tiles);
}

// ---------------- launch ----------------
extern "C" void kernel_launch(void* const* d_in, const int* in_sizes, int n_in,
                              void* d_out, int out_size) {
    const float* q    = (const float*)d_in[0];
    const float* r    = (const float*)d_in[1];
    const float* cell = (const float*)d_in[2];
    float* out = (float*)d_out;

    dim3 tgrid((NATOMS + 255) / 256, 7);
    k_tab<<<tgrid, 256>>>(q, r, cell);
    k_main<<<dim3(BB * 121, 2), NT>>>(q, out);
}